// round 3
// baseline (speedup 1.0000x reference)
#include <cuda_runtime.h>
#include <math.h>

#define NB 4
#define NC 128
#define NP 128
#define ND 128
#define NG 512
#define NROW (NB * NC * NP)            // 65536
#define NELEM ((size_t)NROW * ND)      // 8388608

typedef unsigned long long u64;

// strides
#define S130 130
#define S129 129
#define S66  66

// -------------------- scratch --------------------
__device__ float g_qzn[NELEM];
__device__ float g_xacc[NELEM];
__device__ float g_tu[NELEM];
__device__ float g_tv[NELEM];
__device__ float g_cu[NELEM];
__device__ float g_cv[NELEM];

// -------------------- packed f32x2 helpers --------------------
__device__ __forceinline__ u64 pk2(float lo, float hi) {
    u64 r; asm("mov.b64 %0, {%1,%2};" : "=l"(r) : "f"(lo), "f"(hi)); return r;
}
__device__ __forceinline__ float2 up2(u64 v) {
    float2 f; asm("mov.b64 {%0,%1}, %2;" : "=f"(f.x), "=f"(f.y) : "l"(v)); return f;
}
__device__ __forceinline__ void fma2(u64 &d, u64 a, u64 b) {
    asm("fma.rn.f32x2 %0, %1, %2, %0;" : "+l"(d) : "l"(a), "l"(b));
}

// =====================================================================
// K1: qzn = LN(qz); xacc = 0.5*(qz + unary).  one warp per row.
// =====================================================================
__global__ __launch_bounds__(256) void k_ln_init(
    const float* __restrict__ qz, const float* __restrict__ unary,
    const float* __restrict__ gamma, const float* __restrict__ beta) {
    int row = blockIdx.x * 8 + (threadIdx.x >> 5);
    int lane = threadIdx.x & 31;
    size_t base = (size_t)row * 128 + lane * 4;
    float4 v = *(const float4*)(qz + base);
    float s = v.x + v.y + v.z + v.w;
    float ss = v.x * v.x + v.y * v.y + v.z * v.z + v.w * v.w;
#pragma unroll
    for (int o = 16; o > 0; o >>= 1) {
        s += __shfl_xor_sync(0xffffffffu, s, o);
        ss += __shfl_xor_sync(0xffffffffu, ss, o);
    }
    float m = s * (1.0f / 128.0f);
    float var = ss * (1.0f / 128.0f) - m * m;
    float inv = rsqrtf(var + 1e-5f);
    float4 u = *(const float4*)(unary + base);
    float4 g4 = *(const float4*)(gamma + lane * 4);
    float4 b4 = *(const float4*)(beta + lane * 4);
    float4 qn, xa;
    qn.x = (v.x - m) * inv * g4.x + b4.x;
    qn.y = (v.y - m) * inv * g4.y + b4.y;
    qn.z = (v.z - m) * inv * g4.z + b4.z;
    qn.w = (v.w - m) * inv * g4.w + b4.w;
    xa.x = 0.5f * (v.x + u.x);
    xa.y = 0.5f * (v.y + u.y);
    xa.z = 0.5f * (v.z + u.z);
    xa.w = 0.5f * (v.w + u.w);
    *(float4*)(g_qzn + base) = qn;
    *(float4*)(g_xacc + base) = xa;
}

// =====================================================================
// K2: 4 batched linears. 64 rows/block, 512 threads, 2 CTAs/SM target.
// Xt: k-major [128k][66r] broadcast; Ws: [128o][129k].
// =====================================================================
__global__ __launch_bounds__(512, 2) void k_gemm4(
    const float* __restrict__ w0, const float* __restrict__ w1,
    const float* __restrict__ w2, const float* __restrict__ w3) {
    extern __shared__ float sm[];
    float* Xt = sm;                 // 128 x 66
    float* Ws = sm + 128 * S66;     // 128 x 129
    int tid = threadIdx.x, lane = tid & 31, w = tid >> 5;
    int row0 = blockIdx.x * 64;
    int b = row0 >> 14;
    int which = blockIdx.y;
    const float* W = (which == 0 ? w0 : which == 1 ? w1 : which == 2 ? w2 : w3)
                     + (size_t)b * 16384;
    float* O = (which == 0 ? g_tu : which == 1 ? g_tv : which == 2 ? g_cu : g_cv);

    for (int i = tid; i < 64 * 128; i += 512) {
        int r = i >> 7, k = i & 127;
        Xt[k * S66 + r] = g_qzn[(size_t)(row0 + r) * 128 + k];
    }
    for (int i = tid; i < 16384; i += 512) {
        int r = i >> 7, c = i & 127;
        Ws[r * S129 + c] = W[i];
    }
    __syncthreads();

    int rbase = w * 4;
    u64 acc[2][4];
#pragma unroll
    for (int i = 0; i < 2; i++)
#pragma unroll
        for (int j = 0; j < 4; j++) acc[i][j] = 0ull;

#pragma unroll 4
    for (int k = 0; k < 128; k++) {
        u64 a2[2], bb[4];
#pragma unroll
        for (int i = 0; i < 2; i++)
            a2[i] = *(const u64*)(Xt + k * S66 + rbase + 2 * i);
#pragma unroll
        for (int j = 0; j < 4; j++) {
            float bv = Ws[(lane + 32 * j) * S129 + k];
            bb[j] = pk2(bv, bv);
        }
#pragma unroll
        for (int i = 0; i < 2; i++)
#pragma unroll
            for (int j = 0; j < 4; j++) fma2(acc[i][j], a2[i], bb[j]);
    }
#pragma unroll
    for (int i = 0; i < 2; i++)
#pragma unroll
        for (int j = 0; j < 4; j++) {
            float2 v = up2(acc[i][j]);
            size_t g = (size_t)(row0 + rbase + 2 * i) * 128 + lane + 32 * j;
            O[g] = v.x;
            O[g + 128] = v.y;
        }
}

// =====================================================================
// attention scores + head-avg softmax -> accP registers.
// Ut: k-major [128d][130p] (pre-scaled by 0.25), Vt: k-major [128d][129q].
// accP[q-pair][p] = (1/16)*sum_h softmax_q(...)  (0.5 * head-mean folded)
// warp owns p = rbase .. rbase+3.
// =====================================================================
__device__ __forceinline__ void attn_scores(const float* __restrict__ Ut,
                                            const float* __restrict__ Vt,
                                            u64 accP[2][4], int lane, int rbase) {
#pragma unroll
    for (int i = 0; i < 2; i++)
#pragma unroll
        for (int j = 0; j < 4; j++) accP[i][j] = 0ull;

    for (int h = 0; h < 8; h++) {
        int ho = h * 16;
        u64 s2[2][4];
#pragma unroll
        for (int i = 0; i < 2; i++)
#pragma unroll
            for (int j = 0; j < 4; j++) s2[i][j] = 0ull;
#pragma unroll
        for (int r = 0; r < 16; r++) {
            int k = ho + r;
            u64 a2[2], bb[4];
#pragma unroll
            for (int i = 0; i < 2; i++)
                a2[i] = *(const u64*)(Ut + k * S130 + rbase + 2 * i);
#pragma unroll
            for (int j = 0; j < 4; j++) {
                float bv = Vt[k * S129 + lane + 32 * j];
                bb[j] = pk2(bv, bv);
            }
#pragma unroll
            for (int i = 0; i < 2; i++)
#pragma unroll
                for (int j = 0; j < 4; j++) fma2(s2[i][j], a2[i], bb[j]);
        }
#pragma unroll
        for (int i = 0; i < 2; i++) {
            float2 sv[4];
#pragma unroll
            for (int j = 0; j < 4; j++) sv[j] = up2(s2[i][j]);
            float mx0 = fmaxf(fmaxf(sv[0].x, sv[1].x), fmaxf(sv[2].x, sv[3].x));
            float mx1 = fmaxf(fmaxf(sv[0].y, sv[1].y), fmaxf(sv[2].y, sv[3].y));
#pragma unroll
            for (int o = 16; o > 0; o >>= 1) {
                mx0 = fmaxf(mx0, __shfl_xor_sync(0xffffffffu, mx0, o));
                mx1 = fmaxf(mx1, __shfl_xor_sync(0xffffffffu, mx1, o));
            }
            float e0[4], e1[4];
            float su0 = 0.f, su1 = 0.f;
#pragma unroll
            for (int j = 0; j < 4; j++) {
                e0[j] = __expf(sv[j].x - mx0);
                e1[j] = __expf(sv[j].y - mx1);
                su0 += e0[j]; su1 += e1[j];
            }
#pragma unroll
            for (int o = 16; o > 0; o >>= 1) {
                su0 += __shfl_xor_sync(0xffffffffu, su0, o);
                su1 += __shfl_xor_sync(0xffffffffu, su1, o);
            }
            float inv0 = __fdividef(1.0f, su0 * 16.0f);
            float inv1 = __fdividef(1.0f, su1 * 16.0f);
            u64 ip = pk2(inv0, inv1);
#pragma unroll
            for (int j = 0; j < 4; j++) fma2(accP[i][j], pk2(e0[j], e1[j]), ip);
        }
    }
}

// =====================================================================
// K3: time attention. block=(b,c), 1024 threads.
// R0: Ut/At alias (128x130); R1: Vt(128x129)/Qn(128x128) alias.
// =====================================================================
__global__ __launch_bounds__(1024) void k_time_attn() {
    extern __shared__ float sm[];
    float* R0 = sm;                   // Ut then At, 128*130
    float* R1 = sm + 128 * S130;      // Vt(129) then Qn(128)
    int tid = threadIdx.x, lane = tid & 31, w = tid >> 5;
    int rbase = w * 4;
    size_t base = (size_t)blockIdx.x * 16384;

    for (int i = tid; i < 16384; i += 1024) {
        int p = i >> 7, d = i & 127;
        float tu = g_tu[base + i];
        float tv = g_tv[base + i];
        R0[d * S130 + p] = 0.25f * tu;
        R1[d * S129 + p] = tv;
    }
    __syncthreads();

    u64 accP[2][4];
    attn_scores(R0, R1, accP, lane, rbase);
    __syncthreads();   // everyone done reading Ut/Vt

    // write At (aliases Ut), load Qn (aliases Vt)
#pragma unroll
    for (int i = 0; i < 2; i++)
#pragma unroll
        for (int j = 0; j < 4; j++)
            *(u64*)(R0 + (lane + 32 * j) * S130 + rbase + 2 * i) = accP[i][j];
    for (int i = tid; i < 16384; i += 1024) {
        int p = i >> 7, d = i & 127;
        R1[p * 128 + d] = g_qzn[base + i];
    }
    __syncthreads();

    // PV: m[p][d] = sum_q At[q][p] * Qn[q][d]
    u64 m[2][4];
#pragma unroll
    for (int i = 0; i < 2; i++)
#pragma unroll
        for (int j = 0; j < 4; j++) m[i][j] = 0ull;
#pragma unroll 4
    for (int q = 0; q < 128; q++) {
        u64 a2[2], bb[4];
#pragma unroll
        for (int i = 0; i < 2; i++)
            a2[i] = *(const u64*)(R0 + q * S130 + rbase + 2 * i);
#pragma unroll
        for (int j = 0; j < 4; j++) {
            float bv = R1[q * 128 + lane + 32 * j];
            bb[j] = pk2(bv, bv);
        }
#pragma unroll
        for (int i = 0; i < 2; i++)
#pragma unroll
            for (int j = 0; j < 4; j++) fma2(m[i][j], a2[i], bb[j]);
    }
#pragma unroll
    for (int i = 0; i < 2; i++)
#pragma unroll
        for (int j = 0; j < 4; j++) {
            float2 v = up2(m[i][j]);
            size_t g = base + (size_t)(rbase + 2 * i) * 128 + lane + 32 * j;
            g_xacc[g] += v.x;
            g_xacc[g + 128] += v.y;
        }
}

// =====================================================================
// K4: channel attention. block=(b,p), 1024 threads.
// xacc[b,c,p,d] += At[d][c] * qzn[b,c,p,d]
// =====================================================================
__global__ __launch_bounds__(1024) void k_chan_attn() {
    extern __shared__ float sm[];
    float* R0 = sm;                   // Ut then At (128x130)
    float* R1 = sm + 128 * S130;      // Vt (128x129)
    int tid = threadIdx.x, lane = tid & 31, w = tid >> 5;
    int rbase = w * 4;
    int bp = blockIdx.x;
    int b = bp >> 7, p = bp & 127;
    size_t base = (size_t)b * 2097152 + (size_t)p * 128;

    for (int i = tid; i < 16384; i += 1024) {
        int c = i >> 7, d = i & 127;
        size_t g = base + (size_t)c * 16384 + d;
        R0[d * S130 + c] = 0.25f * g_cu[g];
        R1[d * S129 + c] = g_cv[g];
    }
    __syncthreads();

    u64 accP[2][4];
    attn_scores(R0, R1, accP, lane, rbase);
    __syncthreads();

#pragma unroll
    for (int i = 0; i < 2; i++)
#pragma unroll
        for (int j = 0; j < 4; j++)
            *(u64*)(R0 + (lane + 32 * j) * S130 + rbase + 2 * i) = accP[i][j];
    __syncthreads();

    // elementwise: xacc[c][d] += At[d][c]*qzn[c][d]  (At rows indexed by d)
    for (int i = tid; i < 16384; i += 1024) {
        int c = i >> 7, d = i & 127;
        size_t g = base + (size_t)c * 16384 + d;
        g_xacc[g] += R0[d * S130 + c] * g_qzn[g];
    }
}

// =====================================================================
// K5: topic branch. 128 rows/block, 1024 threads, 512 blocks.
// =====================================================================
__global__ __launch_bounds__(1024) void k_topic(const float* __restrict__ topic) {
    extern __shared__ float sm[];
    float* Qt = sm;                          // [128k][130r]
    float* Tn = Qt + 128 * S130;             // [128g][129d]
    float* St = Tn + 128 * S129;             // [128g][130r]
    float* rs = St + 128 * S130;             // [128]
    int tid = threadIdx.x, lane = tid & 31, w = tid >> 5;
    int rbase = w * 4;
    int row0 = blockIdx.x * 128;
    int b = row0 >> 14;
    const float* Tb = topic + (size_t)b * NG * 128;

    for (int i = tid; i < 16384; i += 1024) {
        int r = i >> 7, k = i & 127;
        Qt[k * S130 + r] = g_qzn[(size_t)(row0 + r) * 128 + k];
    }
    if (tid < 128) rs[tid] = 0.0f;

    u64 macc[2][4];
#pragma unroll
    for (int i = 0; i < 2; i++)
#pragma unroll
        for (int j = 0; j < 4; j++) macc[i][j] = 0ull;

    for (int gc = 0; gc < 4; gc++) {
        __syncthreads();
        for (int i = tid; i < 16384; i += 1024) {
            int g = i >> 7, d = i & 127;
            Tn[g * S129 + d] = Tb[(size_t)(gc * 128 + g) * 128 + d];
        }
        __syncthreads();

        // gemm1: S[r][g] = Q[r][:] . T[g][:]
        u64 s2[2][4];
#pragma unroll
        for (int i = 0; i < 2; i++)
#pragma unroll
            for (int j = 0; j < 4; j++) s2[i][j] = 0ull;
#pragma unroll 4
        for (int k = 0; k < 128; k++) {
            u64 a2[2], bb[4];
#pragma unroll
            for (int i = 0; i < 2; i++)
                a2[i] = *(const u64*)(Qt + k * S130 + rbase + 2 * i);
#pragma unroll
            for (int j = 0; j < 4; j++) {
                float bv = Tn[(lane + 32 * j) * S129 + k];
                bb[j] = pk2(bv, bv);
            }
#pragma unroll
            for (int i = 0; i < 2; i++)
#pragma unroll
                for (int j = 0; j < 4; j++) fma2(s2[i][j], a2[i], bb[j]);
        }
#pragma unroll
        for (int i = 0; i < 2; i++) {
            float2 v[4];
            float su0 = 0.f, su1 = 0.f;
#pragma unroll
            for (int j = 0; j < 4; j++) {
                v[j] = up2(s2[i][j]);
                v[j].x = fmaxf(v[j].x, 0.0f);
                v[j].y = fmaxf(v[j].y, 0.0f);
                su0 += v[j].x; su1 += v[j].y;
            }
#pragma unroll
            for (int o = 16; o > 0; o >>= 1) {
                su0 += __shfl_xor_sync(0xffffffffu, su0, o);
                su1 += __shfl_xor_sync(0xffffffffu, su1, o);
            }
            if (lane == 0) {
                rs[rbase + 2 * i] += su0;
                rs[rbase + 2 * i + 1] += su1;
            }
#pragma unroll
            for (int j = 0; j < 4; j++)
                *(u64*)(St + (lane + 32 * j) * S130 + rbase + 2 * i) = pk2(v[j].x, v[j].y);
        }
        __syncthreads();

        // gemm2: M[r][d] += S[r][g] * T[g][d]
#pragma unroll 4
        for (int g = 0; g < 128; g++) {
            u64 a2[2], bb[4];
#pragma unroll
            for (int i = 0; i < 2; i++)
                a2[i] = *(const u64*)(St + g * S130 + rbase + 2 * i);
#pragma unroll
            for (int j = 0; j < 4; j++) {
                float bv = Tn[g * S129 + lane + 32 * j];
                bb[j] = pk2(bv, bv);
            }
#pragma unroll
            for (int i = 0; i < 2; i++)
#pragma unroll
                for (int j = 0; j < 4; j++) fma2(macc[i][j], a2[i], bb[j]);
        }
    }
    __syncthreads();
#pragma unroll
    for (int i = 0; i < 2; i++) {
        float idn0 = 0.5f / fmaxf(rs[rbase + 2 * i], 1e-6f);
        float idn1 = 0.5f / fmaxf(rs[rbase + 2 * i + 1], 1e-6f);
#pragma unroll
        for (int j = 0; j < 4; j++) {
            float2 v = up2(macc[i][j]);
            size_t g = (size_t)(row0 + rbase + 2 * i) * 128 + lane + 32 * j;
            g_xacc[g] += v.x * idn0;
            g_xacc[g + 128] += v.y * idn1;
        }
    }
}

// =====================================================================
// K6: out = x + gelu(LN(x)@w1^T+b1)@w2^T+b2. 128 rows/block, 1024 thr.
// =====================================================================
__global__ __launch_bounds__(1024) void k_mlp(
    const float* __restrict__ gamma, const float* __restrict__ beta,
    const float* __restrict__ w1, const float* __restrict__ b1,
    const float* __restrict__ w2, const float* __restrict__ b2,
    float* __restrict__ out) {
    extern __shared__ float sm[];
    float* W1n = sm;                        // 128 x 129
    float* W2n = W1n + 128 * S129;          // 128 x 129
    float* Ht  = W2n + 128 * S129;          // [128d][130r], aliased by Tt
    int tid = threadIdx.x, lane = tid & 31, w = tid >> 5;
    int rbase = w * 4;
    int row0 = blockIdx.x * 128;

    for (int i = tid; i < 16384; i += 1024) {
        int r = i >> 7, c = i & 127;
        W1n[r * S129 + c] = w1[i];
        W2n[r * S129 + c] = w2[i];
    }
    float4 g4 = *(const float4*)(gamma + lane * 4);
    float4 b4 = *(const float4*)(beta + lane * 4);
#pragma unroll
    for (int it = 0; it < 4; it++) {
        int r = rbase + it;
        size_t gb = (size_t)(row0 + r) * 128 + lane * 4;
        float4 v = *(const float4*)(g_xacc + gb);
        float s = v.x + v.y + v.z + v.w;
        float ss = v.x * v.x + v.y * v.y + v.z * v.z + v.w * v.w;
#pragma unroll
        for (int o = 16; o > 0; o >>= 1) {
            s += __shfl_xor_sync(0xffffffffu, s, o);
            ss += __shfl_xor_sync(0xffffffffu, ss, o);
        }
        float m = s * (1.0f / 128.0f);
        float var = ss * (1.0f / 128.0f) - m * m;
        float inv = rsqrtf(var + 1e-5f);
        Ht[(lane * 4 + 0) * S130 + r] = (v.x - m) * inv * g4.x + b4.x;
        Ht[(lane * 4 + 1) * S130 + r] = (v.y - m) * inv * g4.y + b4.y;
        Ht[(lane * 4 + 2) * S130 + r] = (v.z - m) * inv * g4.z + b4.z;
        Ht[(lane * 4 + 3) * S130 + r] = (v.w - m) * inv * g4.w + b4.w;
    }
    __syncthreads();

    float bs1[4], bs2[4];
#pragma unroll
    for (int j = 0; j < 4; j++) {
        bs1[j] = b1[lane + 32 * j];
        bs2[j] = b2[lane + 32 * j];
    }

    // gemm1 (reads Ht fully into regs)
    u64 acc[2][4];
#pragma unroll
    for (int i = 0; i < 2; i++)
#pragma unroll
        for (int j = 0; j < 4; j++) acc[i][j] = 0ull;
#pragma unroll 4
    for (int k = 0; k < 128; k++) {
        u64 a2[2], bb[4];
#pragma unroll
        for (int i = 0; i < 2; i++)
            a2[i] = *(const u64*)(Ht + k * S130 + rbase + 2 * i);
#pragma unroll
        for (int j = 0; j < 4; j++) {
            float bv = W1n[(lane + 32 * j) * S129 + k];
            bb[j] = pk2(bv, bv);
        }
#pragma unroll
        for (int i = 0; i < 2; i++)
#pragma unroll
            for (int j = 0; j < 4; j++) fma2(acc[i][j], a2[i], bb[j]);
    }
    __syncthreads();   // all reads of Ht done before overwriting with Tt

    // gelu -> Tt (aliases Ht), k-major [128o][130r]
#pragma unroll
    for (int i = 0; i < 2; i++)
#pragma unroll
        for (int j = 0; j < 4; j++) {
            float2 v = up2(acc[i][j]);
            float x0 = v.x + bs1[j], x1 = v.y + bs1[j];
            float gl0 = 0.5f * x0 * (1.0f + erff(x0 * 0.70710678118654752f));
            float gl1 = 0.5f * x1 * (1.0f + erff(x1 * 0.70710678118654752f));
            *(u64*)(Ht + (lane + 32 * j) * S130 + rbase + 2 * i) = pk2(gl0, gl1);
        }
    __syncthreads();

    // gemm2 -> out
    u64 acc2[2][4];
#pragma unroll
    for (int i = 0; i < 2; i++)
#pragma unroll
        for (int j = 0; j < 4; j++) acc2[i][j] = 0ull;
#pragma unroll 4
    for (int o = 0; o < 128; o++) {
        u64 a2[2], bb[4];
#pragma unroll
        for (int i = 0; i < 2; i++)
            a2[i] = *(const u64*)(Ht + o * S130 + rbase + 2 * i);
#pragma unroll
        for (int j = 0; j < 4; j++) {
            float bv = W2n[(lane + 32 * j) * S129 + o];
            bb[j] = pk2(bv, bv);
        }
#pragma unroll
        for (int i = 0; i < 2; i++)
#pragma unroll
            for (int j = 0; j < 4; j++) fma2(acc2[i][j], a2[i], bb[j]);
    }
#pragma unroll
    for (int i = 0; i < 2; i++)
#pragma unroll
        for (int j = 0; j < 4; j++) {
            float2 v = up2(acc2[i][j]);
            size_t g = (size_t)(row0 + rbase + 2 * i) * 128 + lane + 32 * j;
            out[g] = g_xacc[g] + v.x + bs2[j];
            out[g + 128] = g_xacc[g + 128] + v.y + bs2[j];
        }
}

// =====================================================================
// launch
// =====================================================================
extern "C" void kernel_launch(void* const* d_in, const int* in_sizes, int n_in,
                              void* d_out, int out_size) {
    const float* qz    = (const float*)d_in[0];
    const float* unary = (const float*)d_in[1];
    const float* tuw   = (const float*)d_in[2];
    const float* tvw   = (const float*)d_in[3];
    const float* cuw   = (const float*)d_in[4];
    const float* cvw   = (const float*)d_in[5];
    const float* topic = (const float*)d_in[6];
    const float* gamma = (const float*)d_in[7];
    const float* beta  = (const float*)d_in[8];
    const float* w1    = (const float*)d_in[9];
    const float* b1    = (const float*)d_in[10];
    const float* w2    = (const float*)d_in[11];
    const float* b2    = (const float*)d_in[12];
    float* out = (float*)d_out;

    const int SM2 = (128 * S66 + 128 * S129) * 4;                    // 99840
    const int SMA = (128 * S130 + 128 * S129) * 4;                   // 132608
    const int SM5 = (128 * S130 + 128 * S129 + 128 * S130 + 128) * 4; // 199168
    const int SM6 = (128 * S129 * 2 + 128 * S130) * 4;               // 198656

    cudaFuncSetAttribute(k_gemm4, cudaFuncAttributeMaxDynamicSharedMemorySize, SM2);
    cudaFuncSetAttribute(k_time_attn, cudaFuncAttributeMaxDynamicSharedMemorySize, SMA);
    cudaFuncSetAttribute(k_chan_attn, cudaFuncAttributeMaxDynamicSharedMemorySize, SMA);
    cudaFuncSetAttribute(k_topic, cudaFuncAttributeMaxDynamicSharedMemorySize, SM5);
    cudaFuncSetAttribute(k_mlp, cudaFuncAttributeMaxDynamicSharedMemorySize, SM6);

    k_ln_init<<<NROW / 8, 256>>>(qz, unary, gamma, beta);
    k_gemm4<<<dim3(NROW / 64, 4), 512, SM2>>>(tuw, tvw, cuw, cvw);
    k_time_attn<<<NB * NC, 1024, SMA>>>();
    k_chan_attn<<<NB * NP, 1024, SMA>>>();
    k_topic<<<NROW / 128, 1024, SM5>>>(topic);
    k_mlp<<<NROW / 128, 1024, SM6>>>(gamma, beta, w1, b1, w2, b2, out);
}